// round 8
// baseline (speedup 1.0000x reference)
#include <cuda_runtime.h>
#include <cuda_fp16.h>
#include <cstdint>

#define NB    32
#define NPTS  2048
#define KNN   16
#define NTOT  (NB * NPTS)
#define CH    32
#define HALF  1024           // candidates per half
#define PPB   64             // points per block (x2 halves = 128 threads)
#define SLOT  32             // candidate slots per (point, half)

// Scratch (device globals: no allocation allowed in kernel_launch)
__device__ int   g_idx[NTOT * KNN];
__device__ float g_S1[NTOT * CH];
__device__ float g_R1[NTOT * CH];
__device__ float g_S2[NTOT * CH];
__device__ float g_R2[NTOT * CH];

typedef unsigned long long u64;
typedef unsigned int u32;

// ---------------------------------------------------------------------------
// packed f32x2 helpers (layer kernels)
// ---------------------------------------------------------------------------
__device__ __forceinline__ u64 ffma2(u64 a, u64 b, u64 c) {
    u64 d; asm("fma.rn.f32x2 %0, %1, %2, %3;" : "=l"(d) : "l"(a), "l"(b), "l"(c)); return d;
}
__device__ __forceinline__ u64 fadd2(u64 a, u64 b) {
    u64 d; asm("add.rn.f32x2 %0, %1, %2;" : "=l"(d) : "l"(a), "l"(b)); return d;
}
__device__ __forceinline__ u64 pack2(float lo, float hi) {
    u64 d; asm("mov.b64 %0, {%1, %2};" : "=l"(d) : "f"(lo), "f"(hi)); return d;
}
__device__ __forceinline__ void unpack2(u64 v, float& lo, float& hi) {
    asm("mov.b64 {%0, %1}, %2;" : "=f"(lo), "=f"(hi) : "l"(v));
}

// ---------------------------------------------------------------------------
// small helpers
// ---------------------------------------------------------------------------
__device__ __forceinline__ void ce_f(float& a, float& b) {
    float lo = fminf(a, b), hi = fmaxf(a, b);
    a = lo; b = hi;
}
__device__ __forceinline__ void ce64(u64& a, u64& b) {
    u64 x = a, y = b;
    bool sw = (y < x);
    a = sw ? y : x;
    b = sw ? x : y;
}
__device__ __forceinline__ __half2 h2(u32 v) {
    return *reinterpret_cast<const __half2*>(&v);
}
__device__ __forceinline__ float dist2s(float x, float y, float z,
                                        float xi, float yi, float zi) {
    float dx = x - xi, dy = y - yi, dz = z - zi;
    return fmaf(dz, dz, fmaf(dy, dy, dx * dx));
}

// ---------------------------------------------------------------------------
// kNN. Block = 64 points x 2 candidate-halves (128 threads).
// Pass A: f16 shifted dot-product keys key(j) = |p_j|^2 - 2 p_j.p_i, streamed
//   through 32 depth-1 minima streams per thread. kappa = max of the 16
//   smallest stream minima of the 2-thread union -> VALID upper bound on the
//   true 16th distance (max of any 16 distinct candidate keys is).
// Pass B: collect j with key <= kappa + 2M (f16-error margin) into slots.
// Pass C: exact f32 (d2, j) streaming-insertion top-16 + half merge ->
//   exact result with low-index tie-break (matches jax.lax.top_k).
// ---------------------------------------------------------------------------
__global__ void __launch_bounds__(128, 5)
knn_kernel(const float* __restrict__ pos, int* __restrict__ idx_out) {
    __shared__ __align__(16) __half shx[NPTS], shy[NPTS], shz[NPTS], shw[NPTS]; // 16KB
    __shared__ __align__(16) u32 sbuf[128 * 33];                                // 16.9KB

    const int b     = blockIdx.x >> 5;          // 32 blocks of 64 points per batch
    const int chunk = blockIdx.x & 31;
    const int base  = b * NPTS;
    const int tid   = threadIdx.x;
    const int half  = tid >> 6;                 // 0 or 1
    const int lp    = tid & 63;                 // local point 0..63
    const int li    = chunk * PPB + lp;
    const int j0    = half * HALF;

    for (int t = tid; t < NPTS; t += 128) {
        const float* p = pos + (base + t) * 3;
        float x = p[0], y = p[1], z = p[2];
        shx[t] = __float2half_rn(x);
        shy[t] = __float2half_rn(y);
        shz[t] = __float2half_rn(z);
        shw[t] = __float2half_rn(x * x + y * y + z * z);
    }
    const float xi = pos[(base + li) * 3 + 0];
    const float yi = pos[(base + li) * 3 + 1];
    const float zi = pos[(base + li) * 3 + 2];
    __syncthreads();

    const __half mtwo = __float2half_rn(-2.0f);
    const __half2 m2x = __half2half2(__hmul(__float2half_rn(xi), mtwo));
    const __half2 m2y = __half2half2(__hmul(__float2half_rn(yi), mtwo));
    const __half2 m2z = __half2half2(__hmul(__float2half_rn(zi), mtwo));

    // ---- Pass A: 32 depth-1 minima streams ----
    const __half2 HINF2 = __half2half2(__ushort_as_half(0x7C00));
    __half2 b0[16];
#pragma unroll
    for (int t = 0; t < 16; ++t) b0[t] = HINF2;

#pragma unroll 1
    for (int tile = 0; tile < HALF / 32; ++tile) {
        const int jb = j0 + tile * 32;
#pragma unroll
        for (int g = 0; g < 4; ++g) {
            const int o = jb + 8 * g;
            uint4 xv = *reinterpret_cast<const uint4*>(&shx[o]);
            uint4 yv = *reinterpret_cast<const uint4*>(&shy[o]);
            uint4 zv = *reinterpret_cast<const uint4*>(&shz[o]);
            uint4 wv = *reinterpret_cast<const uint4*>(&shw[o]);
            __half2 k0 = __hfma2(h2(zv.x), m2z, __hfma2(h2(yv.x), m2y, __hfma2(h2(xv.x), m2x, h2(wv.x))));
            __half2 k1 = __hfma2(h2(zv.y), m2z, __hfma2(h2(yv.y), m2y, __hfma2(h2(xv.y), m2x, h2(wv.y))));
            __half2 k2 = __hfma2(h2(zv.z), m2z, __hfma2(h2(yv.z), m2y, __hfma2(h2(xv.z), m2x, h2(wv.z))));
            __half2 k3 = __hfma2(h2(zv.w), m2z, __hfma2(h2(yv.w), m2y, __hfma2(h2(xv.w), m2x, h2(wv.w))));
            b0[4 * g + 0] = __hmin2(b0[4 * g + 0], k0);
            b0[4 * g + 1] = __hmin2(b0[4 * g + 1], k1);
            b0[4 * g + 2] = __hmin2(b0[4 * g + 2], k2);
            b0[4 * g + 3] = __hmin2(b0[4 * g + 3], k3);
        }
    }

    // sort the 32 stream minima ascending
    float v[32];
#pragma unroll
    for (int t = 0; t < 16; ++t) {
        v[2 * t]     = __low2float(b0[t]);
        v[2 * t + 1] = __high2float(b0[t]);
    }
#pragma unroll
    for (int k = 2; k <= 32; k <<= 1) {
#pragma unroll
        for (int s = k >> 1; s > 0; s >>= 1) {
#pragma unroll
            for (int i = 0; i < 32; ++i) {
                int l = i ^ s;
                if (l > i) {
                    if ((i & k) == 0) ce_f(v[i], v[l]);
                    else              ce_f(v[l], v[i]);
                }
            }
        }
    }

    // publish sorted-16; kappa = 16th smallest of the 2-thread union
    float* skap = reinterpret_cast<float*>(sbuf);       // [128] stride 17
#pragma unroll
    for (int q = 0; q < KNN; ++q) skap[tid * 17 + q] = v[q];
    __syncthreads();

    float kap = -3.4e38f;
#pragma unroll
    for (int i = 0; i < KNN; ++i)
        kap = fmaxf(kap, fminf(skap[lp * 17 + i], skap[(lp + 64) * 17 + (KNN - 1 - i)]));

    // margin for f16 key error (cancellation-aware, per-point); same as R7
    const float r  = sqrtf(xi * xi + yi * yi + zi * zi);
    const float M  = 0.003f * (r + 1.6f) * (3.0f * r + 1.6f);
    const float T  = kap + 2.0f * M + 1e-3f;
    const __half2 T2 = __half2half2(__float2half_ru(T));
    __syncthreads();

    // reinit sbuf as candidate slots [128][33]
#pragma unroll
    for (int u = 0; u < SLOT; ++u) sbuf[tid * 33 + u] = 0xFFFFFFFFu;
    __syncthreads();

    // ---- Pass B: collect candidates with key <= T from this half ----
    int cnt = 0;
    const int sb0 = tid * 33;
#pragma unroll 2
    for (int o = j0; o < j0 + HALF; o += 8) {
        uint4 xv = *reinterpret_cast<const uint4*>(&shx[o]);
        uint4 yv = *reinterpret_cast<const uint4*>(&shy[o]);
        uint4 zv = *reinterpret_cast<const uint4*>(&shz[o]);
        uint4 wv = *reinterpret_cast<const uint4*>(&shw[o]);
        __half2 k0 = __hfma2(h2(zv.x), m2z, __hfma2(h2(yv.x), m2y, __hfma2(h2(xv.x), m2x, h2(wv.x))));
        __half2 k1 = __hfma2(h2(zv.y), m2z, __hfma2(h2(yv.y), m2y, __hfma2(h2(xv.y), m2x, h2(wv.y))));
        __half2 k2 = __hfma2(h2(zv.z), m2z, __hfma2(h2(yv.z), m2y, __hfma2(h2(xv.z), m2x, h2(wv.z))));
        __half2 k3 = __hfma2(h2(zv.w), m2z, __hfma2(h2(yv.w), m2y, __hfma2(h2(xv.w), m2x, h2(wv.w))));
        u32 m0 = __hle2_mask(k0, T2);
        u32 m1 = __hle2_mask(k1, T2);
        u32 m2 = __hle2_mask(k2, T2);
        u32 m3 = __hle2_mask(k3, T2);
        if ((m0 | m1 | m2 | m3) == 0u) continue;
        if (m0 & 0x0000FFFFu) { if (cnt < SLOT) sbuf[sb0 + cnt++] = (u32)(o + 0); }
        if (m0 & 0xFFFF0000u) { if (cnt < SLOT) sbuf[sb0 + cnt++] = (u32)(o + 1); }
        if (m1 & 0x0000FFFFu) { if (cnt < SLOT) sbuf[sb0 + cnt++] = (u32)(o + 2); }
        if (m1 & 0xFFFF0000u) { if (cnt < SLOT) sbuf[sb0 + cnt++] = (u32)(o + 3); }
        if (m2 & 0x0000FFFFu) { if (cnt < SLOT) sbuf[sb0 + cnt++] = (u32)(o + 4); }
        if (m2 & 0xFFFF0000u) { if (cnt < SLOT) sbuf[sb0 + cnt++] = (u32)(o + 5); }
        if (m3 & 0x0000FFFFu) { if (cnt < SLOT) sbuf[sb0 + cnt++] = (u32)(o + 6); }
        if (m3 & 0xFFFF0000u) { if (cnt < SLOT) sbuf[sb0 + cnt++] = (u32)(o + 7); }
    }

    // ---- Pass C: exact f32 (d2, j) streaming-insertion top-16 ----
    u64 best[KNN];
#pragma unroll
    for (int q = 0; q < KNN; ++q) best[q] = 0xFFFFFFFFFFFFFFFFull;

#pragma unroll 1
    for (int u = 0; u < SLOT; ++u) {
        u32 jj = sbuf[sb0 + u];
        if (jj == 0xFFFFFFFFu) break;            // slots fill contiguously
        const float* pj = pos + (base + (int)jj) * 3;
        float d2 = dist2s(pj[0], pj[1], pj[2], xi, yi, zi);
        u64 vk = ((u64)__float_as_uint(d2) << 32) | jj;
#pragma unroll
        for (int q = 0; q < KNN; ++q) {
            u64 mn = (vk < best[q]) ? vk : best[q];
            vk     = (vk < best[q]) ? best[q] : vk;
            best[q] = mn;
        }
    }
    __syncthreads();   // all slot reads done; sbuf may be re-aliased

    // ---- merge halves: half1 publishes sorted-16; half0 folds + writes ----
    u64* sped = reinterpret_cast<u64*>(sbuf);          // [64] stride 17 u64
    if (half == 1) {
#pragma unroll
        for (int q = 0; q < KNN; ++q) sped[lp * 17 + q] = best[q];
    }
    __syncthreads();
    if (half == 0) {
        u64 m[KNN];
#pragma unroll
        for (int i = 0; i < KNN; ++i) {
            u64 o = sped[lp * 17 + (KNN - 1 - i)];
            m[i] = (best[i] < o) ? best[i] : o;
        }
#pragma unroll
        for (int s = 8; s > 0; s >>= 1) {
#pragma unroll
            for (int i = 0; i < KNN; ++i) {
                int l = i ^ s;
                if (l > i) ce64(m[i], m[l]);
            }
        }
        const int gi = base + li;
#pragma unroll
        for (int q = 0; q < KNN; ++q)
            idx_out[gi * KNN + q] = base + (int)(u32)(m[q] & 0xFFFFFFFFull);
    }
}

// ---------------------------------------------------------------------------
// Prep for layer 1 (h == p): S1[j] = p_j@(Wh+Wr), R1[i] = p_i@Wr
// ---------------------------------------------------------------------------
__global__ void prep1_kernel(const float* __restrict__ pos,
                             const float* __restrict__ w1a,
                             float* __restrict__ S, float* __restrict__ R) {
    int t = blockIdx.x * blockDim.x + threadIdx.x;
    int node = t >> 5;
    int c    = t & 31;
    float x = pos[node * 3 + 0];
    float y = pos[node * 3 + 1];
    float z = pos[node * 3 + 2];
    float wr0 = w1a[3 * 32 + c], wr1 = w1a[4 * 32 + c], wr2 = w1a[5 * 32 + c];
    float wh0 = w1a[0 * 32 + c] + wr0;
    float wh1 = w1a[1 * 32 + c] + wr1;
    float wh2 = w1a[2 * 32 + c] + wr2;
    S[t] = x * wh0 + y * wh1 + z * wh2;
    R[t] = x * wr0 + y * wr1 + z * wr2;
}

// ---------------------------------------------------------------------------
// Layer 1 + fused prep2. Warp per node:
//   h = relu(max_k( relu(S1[j_k]-R1[i]+b1a) @ w1b ) + b1b)
//   S2[i] = h @ w2a[0:32] + p_i @ w2a[32:35];  R2[i] = p_i @ w2a[32:35]
// ---------------------------------------------------------------------------
__global__ void __launch_bounds__(256)
layer1_fused_kernel(const float* __restrict__ S,
                    const float* __restrict__ R,
                    const float* __restrict__ ba,
                    const float* __restrict__ wb,
                    const float* __restrict__ bb,
                    const int* __restrict__ idx,
                    const float* __restrict__ pos,
                    const float* __restrict__ wnext,     // w2a [35,32]
                    float* __restrict__ Sn, float* __restrict__ Rn) {
    __shared__ __align__(16) float sE[8][KNN][CH];
    const int lane = threadIdx.x & 31;
    const int wid  = threadIdx.x >> 5;
    const int wpb  = blockDim.x >> 5;

    u64 wp[CH / 2];
#pragma unroll
    for (int d = 0; d < CH / 2; ++d)
        wp[d] = pack2(wb[(2 * d) * 32 + lane], wb[(2 * d + 1) * 32 + lane]);
    const float bav = ba[lane];
    const float bbv = bb[lane];

    float wa2[CH];
#pragma unroll
    for (int d = 0; d < CH; ++d) wa2[d] = wnext[d * 32 + lane];
    const float wr0 = wnext[(32 + 0) * 32 + lane];
    const float wr1 = wnext[(32 + 1) * 32 + lane];
    const float wr2 = wnext[(32 + 2) * 32 + lane];

    for (int node = blockIdx.x * wpb + wid; node < NTOT; node += gridDim.x * wpb) {
        const float vb = bav - R[node * 32 + lane];
        const int myj  = idx[node * KNN + (lane & 15)];

#pragma unroll
        for (int k = 0; k < KNN; ++k) {
            int j = __shfl_sync(0xffffffffu, myj, k);
            float e = S[j * 32 + lane] + vb;
            sE[wid][k][lane] = fmaxf(e, 0.0f);
        }
        __syncwarp();

        float mx = -3.4e38f;
#pragma unroll
        for (int k = 0; k < KNN; ++k) {
            const ulonglong2* ek = reinterpret_cast<const ulonglong2*>(&sE[wid][k][0]);
            u64 a0 = 0, a1 = 0, a2 = 0, a3 = 0;
#pragma unroll
            for (int c = 0; c < 4; ++c) {
                ulonglong2 e2a = ek[2 * c + 0];
                ulonglong2 e2b = ek[2 * c + 1];
                a0 = ffma2(e2a.x, wp[4 * c + 0], a0);
                a1 = ffma2(e2a.y, wp[4 * c + 1], a1);
                a2 = ffma2(e2b.x, wp[4 * c + 2], a2);
                a3 = ffma2(e2b.y, wp[4 * c + 3], a3);
            }
            u64 t = fadd2(fadd2(a0, a1), fadd2(a2, a3));
            float lo, hi;
            unpack2(t, lo, hi);
            mx = fmaxf(mx, lo + hi);
        }
        __syncwarp();

        const float h = fmaxf(mx + bbv, 0.0f);

        // fused prep2 (same math & order as the old prep2 kernel)
        float x = pos[node * 3 + 0];
        float y = pos[node * 3 + 1];
        float z = pos[node * 3 + 2];
        float rr = x * wr0 + y * wr1 + z * wr2;
        float acc = rr;
#pragma unroll
        for (int d = 0; d < CH; ++d) {
            float hd = __shfl_sync(0xffffffffu, h, d);
            acc = fmaf(hd, wa2[d], acc);
        }
        Sn[node * 32 + lane] = acc;
        Rn[node * 32 + lane] = rr;
    }
}

// ---------------------------------------------------------------------------
// Layer 2 (final): out = max_k( relu(S2[j_k]-R2[i]+b2a) @ w2b ) + b2b
// ---------------------------------------------------------------------------
__global__ void __launch_bounds__(256)
layer2_kernel(const float* __restrict__ S,
              const float* __restrict__ R,
              const float* __restrict__ ba,
              const float* __restrict__ wb,
              const float* __restrict__ bb,
              const int* __restrict__ idx,
              float* __restrict__ out) {
    __shared__ __align__(16) float sE[8][KNN][CH];
    const int lane = threadIdx.x & 31;
    const int wid  = threadIdx.x >> 5;
    const int wpb  = blockDim.x >> 5;

    u64 wp[CH / 2];
#pragma unroll
    for (int d = 0; d < CH / 2; ++d)
        wp[d] = pack2(wb[(2 * d) * 32 + lane], wb[(2 * d + 1) * 32 + lane]);
    const float bav = ba[lane];
    const float bbv = bb[lane];

    for (int node = blockIdx.x * wpb + wid; node < NTOT; node += gridDim.x * wpb) {
        const float vb = bav - R[node * 32 + lane];
        const int myj  = idx[node * KNN + (lane & 15)];

#pragma unroll
        for (int k = 0; k < KNN; ++k) {
            int j = __shfl_sync(0xffffffffu, myj, k);
            float e = S[j * 32 + lane] + vb;
            sE[wid][k][lane] = fmaxf(e, 0.0f);
        }
        __syncwarp();

        float mx = -3.4e38f;
#pragma unroll
        for (int k = 0; k < KNN; ++k) {
            const ulonglong2* ek = reinterpret_cast<const ulonglong2*>(&sE[wid][k][0]);
            u64 a0 = 0, a1 = 0, a2 = 0, a3 = 0;
#pragma unroll
            for (int c = 0; c < 4; ++c) {
                ulonglong2 e2a = ek[2 * c + 0];
                ulonglong2 e2b = ek[2 * c + 1];
                a0 = ffma2(e2a.x, wp[4 * c + 0], a0);
                a1 = ffma2(e2a.y, wp[4 * c + 1], a1);
                a2 = ffma2(e2b.x, wp[4 * c + 2], a2);
                a3 = ffma2(e2b.y, wp[4 * c + 3], a3);
            }
            u64 t = fadd2(fadd2(a0, a1), fadd2(a2, a3));
            float lo, hi;
            unpack2(t, lo, hi);
            mx = fmaxf(mx, lo + hi);
        }
        __syncwarp();

        out[node * 32 + lane] = mx + bbv;
    }
}

// ---------------------------------------------------------------------------
extern "C" void kernel_launch(void* const* d_in, const int* in_sizes, int n_in,
                              void* d_out, int out_size) {
    const float* pos = (const float*)d_in[0];
    const float* w1a = (const float*)d_in[2];
    const float* b1a = (const float*)d_in[3];
    const float* w1b = (const float*)d_in[4];
    const float* b1b = (const float*)d_in[5];
    const float* w2a = (const float*)d_in[6];
    const float* b2a = (const float*)d_in[7];
    const float* w2b = (const float*)d_in[8];
    const float* b2b = (const float*)d_in[9];
    float* out = (float*)d_out;

    int*   idx; cudaGetSymbolAddress((void**)&idx, g_idx);
    float* S1;  cudaGetSymbolAddress((void**)&S1,  g_S1);
    float* R1;  cudaGetSymbolAddress((void**)&R1,  g_R1);
    float* S2;  cudaGetSymbolAddress((void**)&S2,  g_S2);
    float* R2;  cudaGetSymbolAddress((void**)&R2,  g_R2);

    // 1. kNN graph
    knn_kernel<<<NB * 32, 128>>>(pos, idx);

    // 2. conv1 prep + conv1 (fused with prep for conv2)
    prep1_kernel<<<(NTOT * CH) / 256, 256>>>(pos, w1a, S1, R1);
    layer1_fused_kernel<<<1024, 256>>>(S1, R1, b1a, w1b, b1b, idx, pos, w2a, S2, R2);

    // 3. conv2
    layer2_kernel<<<1024, 256>>>(S2, R2, b2a, w2b, b2b, idx, out);
}